// round 4
// baseline (speedup 1.0000x reference)
#include <cuda_runtime.h>
#include <math.h>

#define BATCH 1024
#define SEQ   250
#define EMB   100
#define UNITS 128
#define GATES 512   // 4*UNITS, gate order i,f,g,o
#define DENSE 32

// Scratch: xz = emb[tokens] @ Wx + b, layout [t][b][512] (524 MB)
__device__ float g_xz[(size_t)SEQ * BATCH * GATES];

// ---- packed f32x2 helpers (sm_100a) --------------------------------------
__device__ __forceinline__ unsigned long long pack2(float a, float b) {
    unsigned long long r;
    asm("mov.b64 %0, {%1, %2};" : "=l"(r) : "f"(a), "f"(b));
    return r;
}
__device__ __forceinline__ void unpack2(unsigned long long v, float& a, float& b) {
    asm("mov.b64 {%0, %1}, %2;" : "=f"(a), "=f"(b) : "l"(v));
}
__device__ __forceinline__ void fma2(unsigned long long& d, unsigned long long a,
                                     unsigned long long b) {
    asm("fma.rn.f32x2 %0, %1, %2, %0;" : "+l"(d) : "l"(a), "l"(b));
}

// ---------------------------------------------------------------------------
// K1: embedding gather + input projection GEMM
//   rows = (b*SEQ + t): 256000 rows, K = 100, N = 512
//   block tile 64 rows x 128 cols, K-chunks of 25, 256 threads.
//   A staged TRANSPOSED in smem (As[e][row]) so row-pairs load packed for
//   f32x2; per-thread micro-tile 8 rows x 4 cols as 4 row-pair x 4 col fma2.
// ---------------------------------------------------------------------------
#define K1_ROWS 64
#define K1_COLS 128
#define K1_KC   25

__global__ __launch_bounds__(256) void k1_embed_proj(
    const int* __restrict__ tokens, const float* __restrict__ emb,
    const float* __restrict__ Wx, const float* __restrict__ bias)
{
    __shared__ float As[K1_KC * K1_ROWS];     // transposed: As[e][row], 6.4 KB
    __shared__ float Bs[K1_KC * K1_COLS];     // Bs[e][col], 12.8 KB
    __shared__ int   tk[K1_ROWS];

    const int tid  = threadIdx.x;
    const int row0 = blockIdx.x * K1_ROWS;    // global row = b*SEQ + t
    const int c0   = blockIdx.y * K1_COLS;

    if (tid < K1_ROWS) tk[tid] = tokens[row0 + tid];

    const int rg = tid >> 5;   // 0..7  -> rows rg*8 .. rg*8+7
    const int cg = tid & 31;   // 0..31 -> cols cg*4 .. cg*4+3

    // acc2[row_pair][col], rows (2rp, 2rp+1) packed
    unsigned long long acc2[4][4];
    {
        const float4 bv = *(const float4*)&bias[c0 + cg * 4];
        #pragma unroll
        for (int rp = 0; rp < 4; rp++) {
            acc2[rp][0] = pack2(bv.x, bv.x);
            acc2[rp][1] = pack2(bv.y, bv.y);
            acc2[rp][2] = pack2(bv.z, bv.z);
            acc2[rp][3] = pack2(bv.w, bv.w);
        }
    }
    __syncthreads();  // tk visible

    for (int kc = 0; kc < EMB; kc += K1_KC) {
        // Gather A chunk transposed: As[e][r] = emb[tk[r]][kc+e]
        // (scattered 4B reads; emb is L2-resident so amplification is cheap)
        for (int idx = tid; idx < K1_KC * K1_ROWS; idx += 256) {
            int e = idx >> 6, r = idx & 63;
            As[idx] = emb[(size_t)tk[r] * EMB + kc + e];
        }
        // B chunk of Wx: Bs[e][col]
        for (int idx = tid; idx < K1_KC * K1_COLS; idx += 256) {
            int e = idx >> 7, j = idx & 127;
            Bs[idx] = Wx[(kc + e) * GATES + c0 + j];
        }
        __syncthreads();

        #pragma unroll
        for (int k = 0; k < K1_KC; k++) {
            // 8 consecutive rows = 4 packed row-pairs, LDS.128 broadcast
            const ulonglong2* ap =
                (const ulonglong2*)&As[k * K1_ROWS + rg * 8];
            ulonglong2 a01 = ap[0];   // rows (0,1),(2,3)
            ulonglong2 a23 = ap[1];   // rows (4,5),(6,7)
            unsigned long long arp[4] = {a01.x, a01.y, a23.x, a23.y};

            float4 b4 = *(const float4*)&Bs[k * K1_COLS + cg * 4];
            unsigned long long bs[4] = {pack2(b4.x, b4.x), pack2(b4.y, b4.y),
                                        pack2(b4.z, b4.z), pack2(b4.w, b4.w)};
            #pragma unroll
            for (int rp = 0; rp < 4; rp++) {
                fma2(acc2[rp][0], arp[rp], bs[0]);
                fma2(acc2[rp][1], arp[rp], bs[1]);
                fma2(acc2[rp][2], arp[rp], bs[2]);
                fma2(acc2[rp][3], arp[rp], bs[3]);
            }
        }
        __syncthreads();
    }

    // Store to [t][b][512]; streaming stores (no reuse before K2).
    #pragma unroll
    for (int rp = 0; rp < 4; rp++) {
        float lo[4], hi[4];
        #pragma unroll
        for (int j = 0; j < 4; j++) unpack2(acc2[rp][j], lo[j], hi[j]);
        #pragma unroll
        for (int h = 0; h < 2; h++) {
            int gr = row0 + rg * 8 + rp * 2 + h;
            int b  = gr / SEQ;
            int t  = gr - b * SEQ;
            size_t off = ((size_t)t * BATCH + b) * GATES + c0 + cg * 4;
            float4 v = h ? make_float4(hi[0], hi[1], hi[2], hi[3])
                         : make_float4(lo[0], lo[1], lo[2], lo[3]);
            __stcs((float4*)&g_xz[off], v);
        }
    }
}

// ---------------------------------------------------------------------------
// K2: LSTM recurrence + dense head
//   128 CTAs x 8 batch rows, 128 threads (1 warp/SMSP).
//   Thread t owns unit u=t, all 4 gates, all 8 rows; row pairs packed f32x2.
//   h stored TRANSPOSED hbuf[unit][row] -> row-pairs load pre-packed via
//   LDS.128 broadcast; Wh read exactly once per CTA-step (coalesced 128B/gate
//   per warp, L1-resident); xz streamed with ldcs to protect L1.
// ---------------------------------------------------------------------------
__device__ __forceinline__ float fast_sigmoid(float x) {
    return 1.0f / (1.0f + __expf(-x));
}
__device__ __forceinline__ float fast_tanh(float x) {
    x = fminf(fmaxf(x, -15.0f), 15.0f);
    float e = __expf(2.0f * x);
    return (e - 1.0f) / (e + 1.0f);
}

__global__ __launch_bounds__(128, 1) void k2_lstm_head(
    const float* __restrict__ Wh,
    const float* __restrict__ W1, const float* __restrict__ b1,
    const float* __restrict__ W2, const float* __restrict__ b2,
    float* __restrict__ out)
{
    __shared__ float hbuf[2][UNITS][8];   // [buf][unit][row], 8 KB
    __shared__ float d1s[8][DENSE];

    const int u  = threadIdx.x;           // unit 0..127
    const int b0 = blockIdx.x * 8;

    *(float4*)&hbuf[0][u][0] = make_float4(0.f, 0.f, 0.f, 0.f);
    *(float4*)&hbuf[0][u][4] = make_float4(0.f, 0.f, 0.f, 0.f);
    float c[8];
    #pragma unroll
    for (int r = 0; r < 8; r++) c[r] = 0.0f;
    __syncthreads();

    const float* whu = Wh + u;            // Wh[k][g*128+u]

    int cur = 0;
    for (int t = 0; t < SEQ; t++) {
        // z[row_pair][gate], seeded from precomputed xz (bias folded in K1)
        unsigned long long z[4][4];
        {
            const float* xzb = &g_xz[((size_t)t * BATCH + b0) * GATES + u];
            #pragma unroll
            for (int rp = 0; rp < 4; rp++)
                #pragma unroll
                for (int g = 0; g < 4; g++) {
                    float lo = __ldcs(xzb + (size_t)(2 * rp)     * GATES + g * UNITS);
                    float hi = __ldcs(xzb + (size_t)(2 * rp + 1) * GATES + g * UNITS);
                    z[rp][g] = pack2(lo, hi);
                }
        }

        const float (*hb)[8] = hbuf[cur];
        #pragma unroll 4
        for (int k = 0; k < UNITS; k++) {
            // 8 rows of h for unit k, pre-packed as 4 row pairs (broadcast)
            const ulonglong2* hp2 = (const ulonglong2*)&hb[k][0];
            ulonglong2 hA = hp2[0], hB = hp2[1];
            unsigned long long hp[4] = {hA.x, hA.y, hB.x, hB.y};

            const float* wk = whu + (size_t)k * GATES;
            #pragma unroll
            for (int g = 0; g < 4; g++) {
                float w = wk[g * UNITS];
                unsigned long long wp = pack2(w, w);
                fma2(z[0][g], hp[0], wp);
                fma2(z[1][g], hp[1], wp);
                fma2(z[2][g], hp[2], wp);
                fma2(z[3][g], hp[3], wp);
            }
        }

        // gate math + h write (transposed, contiguous for this thread)
        const int nxt = cur ^ 1;
        float hv[8];
        #pragma unroll
        for (int rp = 0; rp < 4; rp++) {
            float zi[2][4];
            #pragma unroll
            for (int g = 0; g < 4; g++) unpack2(z[rp][g], zi[0][g], zi[1][g]);
            #pragma unroll
            for (int h = 0; h < 2; h++) {
                int r = 2 * rp + h;
                float ig = fast_sigmoid(zi[h][0]);
                float fg = fast_sigmoid(zi[h][1]);
                float gg = fast_tanh   (zi[h][2]);
                float og = fast_sigmoid(zi[h][3]);
                float cc = fg * c[r] + ig * gg;
                c[r] = cc;
                hv[r] = og * fast_tanh(cc);
            }
        }
        *(float4*)&hbuf[nxt][u][0] = make_float4(hv[0], hv[1], hv[2], hv[3]);
        *(float4*)&hbuf[nxt][u][4] = make_float4(hv[4], hv[5], hv[6], hv[7]);
        __syncthreads();
        cur = nxt;
    }

    // ---- dense head: relu(h @ W1 + b1) @ W2 + b2, softmax ----
    {
        int r  = u >> 4;              // 0..7
        int jj = (u & 15) * 2;        // dense units jj, jj+1
        float a0 = b1[jj], a1 = b1[jj + 1];
        #pragma unroll 8
        for (int k = 0; k < UNITS; k++) {
            float h = hbuf[cur][k][r];
            a0 += h * W1[k * DENSE + jj];
            a1 += h * W1[k * DENSE + jj + 1];
        }
        d1s[r][jj]     = fmaxf(a0, 0.0f);
        d1s[r][jj + 1] = fmaxf(a1, 0.0f);
    }
    __syncthreads();
    if (u < 8) {
        float l0 = b2[0], l1 = b2[1];
        #pragma unroll
        for (int j = 0; j < DENSE; j++) {
            float d = d1s[u][j];
            l0 += d * W2[j * 2 + 0];
            l1 += d * W2[j * 2 + 1];
        }
        float m  = fmaxf(l0, l1);
        float e0 = __expf(l0 - m), e1 = __expf(l1 - m);
        float s  = 1.0f / (e0 + e1);
        out[(b0 + u) * 2 + 0] = e0 * s;
        out[(b0 + u) * 2 + 1] = e1 * s;
    }
}

// ---------------------------------------------------------------------------
extern "C" void kernel_launch(void* const* d_in, const int* in_sizes, int n_in,
                              void* d_out, int out_size)
{
    const int*   tokens = (const int*)  d_in[0];
    const float* emb    = (const float*)d_in[1];
    const float* Wx     = (const float*)d_in[2];
    const float* Wh     = (const float*)d_in[3];
    const float* lb     = (const float*)d_in[4];
    const float* W1     = (const float*)d_in[5];
    const float* b1     = (const float*)d_in[6];
    const float* W2     = (const float*)d_in[7];
    const float* b2     = (const float*)d_in[8];
    float* out = (float*)d_out;

    dim3 g1(BATCH * SEQ / K1_ROWS, GATES / K1_COLS);   // (4000, 4)
    k1_embed_proj<<<g1, 256>>>(tokens, emb, Wx, lb);
    k2_lstm_head<<<BATCH / 8, 128>>>(Wh, W1, b1, W2, b2, out);
}

// round 5
// speedup vs baseline: 1.6863x; 1.6863x over previous
#include <cuda_runtime.h>
#include <math.h>

#define BATCH 1024
#define SEQ   250
#define EMB   100
#define UNITS 128
#define GATES 512   // 4*UNITS, gate order i,f,g,o
#define DENSE 32

// Scratch: xz = emb[tokens] @ Wx + b, layout [t][b][512] (524 MB)
__device__ float g_xz[(size_t)SEQ * BATCH * GATES];

// ---- packed f32x2 helpers (sm_100a) --------------------------------------
__device__ __forceinline__ unsigned long long pack2(float a, float b) {
    unsigned long long r;
    asm("mov.b64 %0, {%1, %2};" : "=l"(r) : "f"(a), "f"(b));
    return r;
}
__device__ __forceinline__ void unpack2(unsigned long long v, float& a, float& b) {
    asm("mov.b64 {%0, %1}, %2;" : "=f"(a), "=f"(b) : "l"(v));
}
__device__ __forceinline__ void fma2(unsigned long long& d, unsigned long long a,
                                     unsigned long long b) {
    asm("fma.rn.f32x2 %0, %1, %2, %0;" : "+l"(d) : "l"(a), "l"(b));
}
__device__ __forceinline__ void add2(unsigned long long& d, unsigned long long a) {
    asm("add.rn.f32x2 %0, %0, %1;" : "+l"(d) : "l"(a));
}

// ---------------------------------------------------------------------------
// K1: embedding gather + input projection GEMM (unchanged from R4 pass)
// ---------------------------------------------------------------------------
#define K1_ROWS 64
#define K1_COLS 128
#define K1_KC   25

__global__ __launch_bounds__(256) void k1_embed_proj(
    const int* __restrict__ tokens, const float* __restrict__ emb,
    const float* __restrict__ Wx, const float* __restrict__ bias)
{
    __shared__ float As[K1_KC * K1_ROWS];     // transposed: As[e][row]
    __shared__ float Bs[K1_KC * K1_COLS];     // Bs[e][col]
    __shared__ int   tk[K1_ROWS];

    const int tid  = threadIdx.x;
    const int row0 = blockIdx.x * K1_ROWS;
    const int c0   = blockIdx.y * K1_COLS;

    if (tid < K1_ROWS) tk[tid] = tokens[row0 + tid];

    const int rg = tid >> 5;
    const int cg = tid & 31;

    unsigned long long acc2[4][4];
    {
        const float4 bv = *(const float4*)&bias[c0 + cg * 4];
        #pragma unroll
        for (int rp = 0; rp < 4; rp++) {
            acc2[rp][0] = pack2(bv.x, bv.x);
            acc2[rp][1] = pack2(bv.y, bv.y);
            acc2[rp][2] = pack2(bv.z, bv.z);
            acc2[rp][3] = pack2(bv.w, bv.w);
        }
    }
    __syncthreads();

    for (int kc = 0; kc < EMB; kc += K1_KC) {
        for (int idx = tid; idx < K1_KC * K1_ROWS; idx += 256) {
            int e = idx >> 6, r = idx & 63;
            As[idx] = emb[(size_t)tk[r] * EMB + kc + e];
        }
        for (int idx = tid; idx < K1_KC * K1_COLS; idx += 256) {
            int e = idx >> 7, j = idx & 127;
            Bs[idx] = Wx[(kc + e) * GATES + c0 + j];
        }
        __syncthreads();

        #pragma unroll
        for (int k = 0; k < K1_KC; k++) {
            const ulonglong2* ap = (const ulonglong2*)&As[k * K1_ROWS + rg * 8];
            ulonglong2 a01 = ap[0];
            ulonglong2 a23 = ap[1];
            unsigned long long arp[4] = {a01.x, a01.y, a23.x, a23.y};

            float4 b4 = *(const float4*)&Bs[k * K1_COLS + cg * 4];
            unsigned long long bs[4] = {pack2(b4.x, b4.x), pack2(b4.y, b4.y),
                                        pack2(b4.z, b4.z), pack2(b4.w, b4.w)};
            #pragma unroll
            for (int rp = 0; rp < 4; rp++) {
                fma2(acc2[rp][0], arp[rp], bs[0]);
                fma2(acc2[rp][1], arp[rp], bs[1]);
                fma2(acc2[rp][2], arp[rp], bs[2]);
                fma2(acc2[rp][3], arp[rp], bs[3]);
            }
        }
        __syncthreads();
    }

    #pragma unroll
    for (int rp = 0; rp < 4; rp++) {
        float lo[4], hi[4];
        #pragma unroll
        for (int j = 0; j < 4; j++) unpack2(acc2[rp][j], lo[j], hi[j]);
        #pragma unroll
        for (int h = 0; h < 2; h++) {
            int gr = row0 + rg * 8 + rp * 2 + h;
            int b  = gr / SEQ;
            int t  = gr - b * SEQ;
            size_t off = ((size_t)t * BATCH + b) * GATES + c0 + cg * 4;
            float4 v = h ? make_float4(hi[0], hi[1], hi[2], hi[3])
                         : make_float4(lo[0], lo[1], lo[2], lo[3]);
            __stcs((float4*)&g_xz[off], v);
        }
    }
}

// ---------------------------------------------------------------------------
// K2: LSTM recurrence + dense head (v2)
//   128 CTAs x 8 batch rows, 256 threads = 8 warps.
//   Thread (u = tid&127, kh = tid>>7) accumulates z over k in [kh*64, kh*64+64)
//   for unit u, 4 gates, all 8 rows (f32x2 row pairs). Partial exchange via
//   padded smem; gate math row-split (kh owns rows kh*4..kh*4+3).
//   Wh: 96 k's staged in smem transposed as [k][u][4 gates] (one LDS.128 per
//   k), 32 residual k's stream from L2 (under the chip LTS cap).
// ---------------------------------------------------------------------------
#define K2_SMEM_KH   48   // smem-resident k's per k-half
#define K2_WHS_BYTES (2 * K2_SMEM_KH * UNITS * 4 * 4)        // 196608
#define K2_HBUF_OFF  K2_WHS_BYTES
#define K2_PART_OFF  (K2_HBUF_OFF + 2 * UNITS * 8 * 4)       // +8192
#define K2_D1S_OFF   (K2_PART_OFF + 256 * 10 * 8)            // +20480
#define K2_SMEM_TOT  (K2_D1S_OFF + 8 * DENSE * 4)            // 226304

__device__ __forceinline__ float fast_sigmoid(float x) {
    return 1.0f / (1.0f + __expf(-x));
}
__device__ __forceinline__ float fast_tanh(float x) {
    x = fminf(fmaxf(x, -15.0f), 15.0f);
    float e = __expf(2.0f * x);
    return (e - 1.0f) / (e + 1.0f);
}

__global__ __launch_bounds__(256, 1) void k2_lstm_head(
    const float* __restrict__ Wh,
    const float* __restrict__ W1, const float* __restrict__ b1,
    const float* __restrict__ W2, const float* __restrict__ b2,
    float* __restrict__ out)
{
    extern __shared__ unsigned char smem_raw[];
    float* whs = (float*)smem_raw;                                   // [96][128][4]
    float (*hbuf)[UNITS][8] = (float (*)[UNITS][8])(smem_raw + K2_HBUF_OFF);
    unsigned long long (*part)[10] =
        (unsigned long long (*)[10])(smem_raw + K2_PART_OFF);        // 80B rows
    float (*d1s)[DENSE] = (float (*)[DENSE])(smem_raw + K2_D1S_OFF);

    const int tid = threadIdx.x;
    const int u   = tid & 127;
    const int kh  = tid >> 7;          // warp-uniform
    const int b0  = blockIdx.x * 8;

    // Stage Wh transposed into smem: slot s -> k = (s/48)*64 + s%48,
    // whs[s][u][g] = Wh[k][g*128+u]
    for (int idx = tid; idx < 2 * K2_SMEM_KH * UNITS; idx += 256) {
        int s  = idx >> 7;
        int uu = idx & 127;
        int k  = (s / K2_SMEM_KH) * 64 + (s % K2_SMEM_KH);
        float4 w;
        w.x = Wh[(size_t)k * GATES + 0 * UNITS + uu];
        w.y = Wh[(size_t)k * GATES + 1 * UNITS + uu];
        w.z = Wh[(size_t)k * GATES + 2 * UNITS + uu];
        w.w = Wh[(size_t)k * GATES + 3 * UNITS + uu];
        *(float4*)&whs[(size_t)idx * 4] = w;
    }

    *(float4*)&hbuf[0][u][(tid >> 7) * 4] = make_float4(0.f, 0.f, 0.f, 0.f);
    float c[4];
    #pragma unroll
    for (int j = 0; j < 4; j++) c[j] = 0.0f;
    __syncthreads();

    const int k0 = kh * 64;
    const float4* wts = (const float4*)whs + (size_t)kh * K2_SMEM_KH * UNITS + u;
    const float*  wg  = Wh + (size_t)(k0 + K2_SMEM_KH) * GATES + u;  // residual k's

    int cur = 0;
    for (int t = 0; t < SEQ; t++) {
        // z[row_pair][gate]; kh=0 seeds with precomputed xz (bias folded in K1)
        unsigned long long z[4][4];
        if (kh == 0) {
            const float* xzb = &g_xz[((size_t)t * BATCH + b0) * GATES + u];
            #pragma unroll
            for (int rp = 0; rp < 4; rp++)
                #pragma unroll
                for (int g = 0; g < 4; g++) {
                    float lo = __ldcs(xzb + (size_t)(2 * rp)     * GATES + g * UNITS);
                    float hi = __ldcs(xzb + (size_t)(2 * rp + 1) * GATES + g * UNITS);
                    z[rp][g] = pack2(lo, hi);
                }
        } else {
            #pragma unroll
            for (int rp = 0; rp < 4; rp++)
                #pragma unroll
                for (int g = 0; g < 4; g++) z[rp][g] = 0ull;
        }

        const float (*hb)[8] = hbuf[cur];

        // smem-resident k's
        #pragma unroll 8
        for (int kk = 0; kk < K2_SMEM_KH; kk++) {
            const ulonglong2* hp2 = (const ulonglong2*)&hb[k0 + kk][0];
            ulonglong2 hA = hp2[0], hB = hp2[1];
            unsigned long long hp[4] = {hA.x, hA.y, hB.x, hB.y};

            float4 w4 = wts[(size_t)kk * UNITS];
            unsigned long long wp[4] = {pack2(w4.x, w4.x), pack2(w4.y, w4.y),
                                        pack2(w4.z, w4.z), pack2(w4.w, w4.w)};
            #pragma unroll
            for (int g = 0; g < 4; g++) {
                fma2(z[0][g], hp[0], wp[g]);
                fma2(z[1][g], hp[1], wp[g]);
                fma2(z[2][g], hp[2], wp[g]);
                fma2(z[3][g], hp[3], wp[g]);
            }
        }
        // residual k's from global (L2)
        #pragma unroll 8
        for (int kk = K2_SMEM_KH; kk < 64; kk++) {
            const ulonglong2* hp2 = (const ulonglong2*)&hb[k0 + kk][0];
            ulonglong2 hA = hp2[0], hB = hp2[1];
            unsigned long long hp[4] = {hA.x, hA.y, hB.x, hB.y};

            const float* wk = wg + (size_t)(kk - K2_SMEM_KH) * GATES;
            #pragma unroll
            for (int g = 0; g < 4; g++) {
                float w = __ldg(wk + g * UNITS);
                unsigned long long wp = pack2(w, w);
                fma2(z[0][g], hp[0], wp);
                fma2(z[1][g], hp[1], wp);
                fma2(z[2][g], hp[2], wp);
                fma2(z[3][g], hp[3], wp);
            }
        }

        // exchange partials for the row-pairs the other half owns
        {
            const int nrp = (kh ^ 1) * 2;
            ulonglong2* ps = (ulonglong2*)part[(kh ^ 1) * 128 + u];
            ps[0] = make_ulonglong2(z[nrp][0],     z[nrp][1]);
            ps[1] = make_ulonglong2(z[nrp][2],     z[nrp][3]);
            ps[2] = make_ulonglong2(z[nrp + 1][0], z[nrp + 1][1]);
            ps[3] = make_ulonglong2(z[nrp + 1][2], z[nrp + 1][3]);
        }
        __syncthreads();
        const int orp = kh * 2;
        {
            const ulonglong2* pm = (const ulonglong2*)part[kh * 128 + u];
            ulonglong2 p0 = pm[0], p1 = pm[1], p2 = pm[2], p3 = pm[3];
            add2(z[orp][0], p0.x);     add2(z[orp][1], p0.y);
            add2(z[orp][2], p1.x);     add2(z[orp][3], p1.y);
            add2(z[orp + 1][0], p2.x); add2(z[orp + 1][1], p2.y);
            add2(z[orp + 1][2], p3.x); add2(z[orp + 1][3], p3.y);
        }

        // gate math for owned rows kh*4 .. kh*4+3
        const int nxt = cur ^ 1;
        float hv[4];
        #pragma unroll
        for (int rr = 0; rr < 2; rr++) {
            float zi[2][4];
            #pragma unroll
            for (int g = 0; g < 4; g++) unpack2(z[orp + rr][g], zi[0][g], zi[1][g]);
            #pragma unroll
            for (int h = 0; h < 2; h++) {
                int j = rr * 2 + h;
                float ig = fast_sigmoid(zi[h][0]);
                float fg = fast_sigmoid(zi[h][1]);
                float gg = fast_tanh   (zi[h][2]);
                float og = fast_sigmoid(zi[h][3]);
                float cc = fg * c[j] + ig * gg;
                c[j] = cc;
                hv[j] = og * fast_tanh(cc);
            }
        }
        *(float4*)&hbuf[nxt][u][kh * 4] = make_float4(hv[0], hv[1], hv[2], hv[3]);
        __syncthreads();
        cur = nxt;
    }

    // ---- dense head: relu(h @ W1 + b1) @ W2 + b2, softmax ----
    {
        int r = tid >> 5;            // 0..7
        int j = tid & 31;            // 0..31
        float a = b1[j];
        #pragma unroll 8
        for (int k = 0; k < UNITS; k++) a += hbuf[cur][k][r] * W1[k * DENSE + j];
        d1s[r][j] = fmaxf(a, 0.0f);
    }
    __syncthreads();
    if (tid < 8) {
        float l0 = b2[0], l1 = b2[1];
        #pragma unroll
        for (int j = 0; j < DENSE; j++) {
            float d = d1s[tid][j];
            l0 += d * W2[j * 2 + 0];
            l1 += d * W2[j * 2 + 1];
        }
        float m  = fmaxf(l0, l1);
        float e0 = __expf(l0 - m), e1 = __expf(l1 - m);
        float s  = 1.0f / (e0 + e1);
        out[(b0 + tid) * 2 + 0] = e0 * s;
        out[(b0 + tid) * 2 + 1] = e1 * s;
    }
}

// ---------------------------------------------------------------------------
extern "C" void kernel_launch(void* const* d_in, const int* in_sizes, int n_in,
                              void* d_out, int out_size)
{
    const int*   tokens = (const int*)  d_in[0];
    const float* emb    = (const float*)d_in[1];
    const float* Wx     = (const float*)d_in[2];
    const float* Wh     = (const float*)d_in[3];
    const float* lb     = (const float*)d_in[4];
    const float* W1     = (const float*)d_in[5];
    const float* b1     = (const float*)d_in[6];
    const float* W2     = (const float*)d_in[7];
    const float* b2     = (const float*)d_in[8];
    float* out = (float*)d_out;

    cudaFuncSetAttribute(k2_lstm_head,
                         cudaFuncAttributeMaxDynamicSharedMemorySize, K2_SMEM_TOT);

    dim3 g1(BATCH * SEQ / K1_ROWS, GATES / K1_COLS);   // (4000, 4)
    k1_embed_proj<<<g1, 256>>>(tokens, emb, Wx, lb);
    k2_lstm_head<<<BATCH / 8, 256, K2_SMEM_TOT>>>(Wh, W1, b1, W2, b2, out);
}